// round 3
// baseline (speedup 1.0000x reference)
#include <cuda_runtime.h>
#include <math.h>

#define TINF 3.0e38f
#define TT   1024
#define BB   32
#define DDIM 64
#define NDIAG (2*TT-1)   // 2047
#define PF   8           // cost prefetch depth (register ring)
#define DEPTH 64         // mailbox ring depth (power of 2)

// Scratch: diag-major cost [b][d][j], d padded to 2048, plus 64-diag tail pad
// (DP loop runs to d=2047 and prefetches to d+PF).
__device__ float g_cost[(size_t)BB * 2048 * TT + 64 * TT];
__device__ float g_n2[2 * BB * TT];   // a2 (first half) then b2
__device__ float g_bdist[BB];

// ---------------------------------------------------------------------------
// Kernel 1: squared row norms. One warp per 64-dim row.
// ---------------------------------------------------------------------------
__global__ void norms_kernel(const float* __restrict__ pred,
                             const float* __restrict__ targ) {
    int gw   = (blockIdx.x * blockDim.x + threadIdx.x) >> 5;
    int lane = threadIdx.x & 31;
    if (gw >= 2 * BB * TT) return;
    const float* src = (gw < BB * TT) ? (pred + (size_t)gw * DDIM)
                                      : (targ + (size_t)(gw - BB * TT) * DDIM);
    float x0 = src[lane], x1 = src[lane + 32];
    float s = x0 * x0 + x1 * x1;
    #pragma unroll
    for (int o = 16; o > 0; o >>= 1) s += __shfl_down_sync(0xffffffffu, s, o);
    if (lane == 0) g_n2[gw] = s;
}

// ---------------------------------------------------------------------------
// Kernel 2: cost tiles. 64x64 tile per block (256 threads, 4x4 microtile),
// epilogue stages the tile in smem and writes diagonal-major runs (coalesced).
// ---------------------------------------------------------------------------
__global__ void __launch_bounds__(256) cost_kernel(const float* __restrict__ pred,
                                                   const float* __restrict__ targ) {
    int jt = blockIdx.x, it = blockIdx.y, b = blockIdx.z;
    int i0 = it * 64, j0 = jt * 64;
    const float* A  = pred + (size_t)b * TT * DDIM;
    const float* Bm = targ + (size_t)b * TT * DDIM;

    __shared__ float sm[8192];          // sA[64k][64i] | sB[64k][64j]; Cs reuses front
    float* sA = sm;
    float* sB = sm + 4096;

    int tid = threadIdx.x;

    for (int f = tid; f < 1024; f += 256) {
        int r = f >> 4;
        int k4 = (f & 15) * 4;
        float4 va = *(const float4*)(A  + (size_t)(i0 + r) * DDIM + k4);
        sA[(k4 + 0) * 64 + r] = va.x;
        sA[(k4 + 1) * 64 + r] = va.y;
        sA[(k4 + 2) * 64 + r] = va.z;
        sA[(k4 + 3) * 64 + r] = va.w;
        float4 vb = *(const float4*)(Bm + (size_t)(j0 + r) * DDIM + k4);
        sB[(k4 + 0) * 64 + r] = vb.x;
        sB[(k4 + 1) * 64 + r] = vb.y;
        sB[(k4 + 2) * 64 + r] = vb.z;
        sB[(k4 + 3) * 64 + r] = vb.w;
    }
    __syncthreads();

    int tx = tid & 15, ty = tid >> 4;
    float acc[16];
    #pragma unroll
    for (int i = 0; i < 16; ++i) acc[i] = 0.f;

    #pragma unroll 8
    for (int k = 0; k < 64; ++k) {
        float4 a  = *(const float4*)(sA + k * 64 + ty * 4);
        float4 bv = *(const float4*)(sB + k * 64 + tx * 4);
        acc[ 0] += a.x * bv.x;  acc[ 1] += a.x * bv.y;
        acc[ 2] += a.x * bv.z;  acc[ 3] += a.x * bv.w;
        acc[ 4] += a.y * bv.x;  acc[ 5] += a.y * bv.y;
        acc[ 6] += a.y * bv.z;  acc[ 7] += a.y * bv.w;
        acc[ 8] += a.z * bv.x;  acc[ 9] += a.z * bv.y;
        acc[10] += a.z * bv.z;  acc[11] += a.z * bv.w;
        acc[12] += a.w * bv.x;  acc[13] += a.w * bv.y;
        acc[14] += a.w * bv.z;  acc[15] += a.w * bv.w;
    }

    const float* a2p = g_n2 + b * TT;
    const float* b2p = g_n2 + BB * TT + b * TT;
    float a2v[4], b2v[4];
    #pragma unroll
    for (int e = 0; e < 4; ++e) a2v[e] = a2p[i0 + ty * 4 + e];
    #pragma unroll
    for (int f = 0; f < 4; ++f) b2v[f] = b2p[j0 + tx * 4 + f];

    __syncthreads();   // reuse sm as Cs (stride 66: diag-gather conflict-free)
    float* Cs = sm;
    #pragma unroll
    for (int e = 0; e < 4; ++e) {
        #pragma unroll
        for (int f = 0; f < 4; ++f) {
            float sq = a2v[e] + b2v[f] - 2.0f * acc[e * 4 + f];
            Cs[(ty * 4 + e) * 66 + (tx * 4 + f)] = sqrtf(fmaxf(sq, 1e-12f));
        }
    }
    __syncthreads();

    float* out = g_cost + (size_t)b * 2048 * TT;
    int warp = tid >> 5, lane = tid & 31;
    int D0 = i0 + j0;
    for (int dd = warp; dd < 127; dd += 8) {
        int jl = max(0, dd - 63);
        int jh = min(dd, 63);
        int L = jh - jl + 1;
        size_t gb = (size_t)(D0 + dd) * TT + (size_t)(j0 + jl);
        for (int l = lane; l < L; l += 32) {
            int j = jl + l;
            out[gb + l] = Cs[(dd - j) * 66 + j];
        }
    }
}

// ---------------------------------------------------------------------------
// Kernel 3: barrier-free wavefront DP. 8 warps x 32 lanes x 4 cols = 1024.
// Intra-warp boundary: one shfl_up per diagonal (qm1 = last iter's pm1).
// Cross-warp boundary: skewed pipeline via 8-byte atomic (tag|value) smem
// mailboxes; lane 0 polls the tag, lane 31 publishes. No __syncthreads in the
// main loop. n3 (the forwarded value) has no transport dependency, so the
// shfl/mailbox latency amortizes over 4 diagonals of local compute.
// ---------------------------------------------------------------------------
__global__ void __launch_bounds__(256, 1) dp_kernel() {
    int b    = blockIdx.x;
    const float* SC = g_cost + (size_t)b * 2048 * TT;
    int t    = threadIdx.x;
    int w    = t >> 5;
    int lane = t & 31;
    int j0   = t << 2;

    __shared__ unsigned long long mb[8][DEPTH];  // [producer warp][d % DEPTH] = (tag<<32)|valbits
    __shared__ int prog[8];                      // latest diag completed by warp w

    for (int i = lane; i < DEPTH; i += 32)
        mb[w][i] = 0xFFFFFFFF00000000ULL;        // tag = -1 (never matches d>=0)
    if (lane == 0) ((volatile int*)prog)[w] = -1;
    __syncthreads();                             // one-time: mailboxes visible

    float4 cbuf[PF];
    #pragma unroll
    for (int d = 0; d < PF; ++d)
        cbuf[d] = *(const float4*)(SC + (size_t)d * TT + j0);

    float p0 = TINF, p1 = TINF, p2 = TINF, p3 = TINF;   // diag d-1
    float q0 = TINF, q1 = TINF, q2 = TINF, q3 = TINF;   // diag d-2
    float qm1 = TINF;                                   // left-neighbor value @ d-2
    float res = 0.f;

    for (int db = 0; db < 2048; db += PF) {             // 2048 = 256*8 >= NDIAG
        // Backpressure: ensure consumer warp (w+1) is within DEPTH-10 diagonals
        // so the slot we are about to overwrite is dead. Checked once per 8.
        if (w < 7 && lane == 31) {
            int need = db - (DEPTH - 10);
            while (((volatile int*)prog)[w + 1] < need) { }
        }
        #pragma unroll
        for (int u = 0; u < PF; ++u) {
            int d = db + u;
            float4 c = cbuf[u];                          // static index
            cbuf[u] = *(const float4*)(SC + (size_t)(d + PF) * TT + j0);

            // Validity: cell (i=d-j, j) valid iff j<=d and j>=d-1023.
            int jlo = d - (TT - 1);
            float c0 = (j0 + 0 <= d && j0 + 0 >= jlo) ? c.x : TINF;
            float c1 = (j0 + 1 <= d && j0 + 1 >= jlo) ? c.y : TINF;
            float c2 = (j0 + 2 <= d && j0 + 2 >= jlo) ? c.z : TINF;
            float c3 = (j0 + 3 <= d && j0 + 3 >= jlo) ? c.w : TINF;

            // Local cells first (no transport dependency), publish n3 ASAP.
            float m3 = fminf(fminf(p3, p2), q2);
            float n3 = fmaxf(c3, m3);
            if (lane == 31)
                *(volatile unsigned long long*)&mb[w][d & (DEPTH - 1)] =
                    (((unsigned long long)(unsigned)d) << 32) | __float_as_uint(n3);

            float m1 = fminf(fminf(p1, p0), q0);
            float m2 = fminf(fminf(p2, p1), q1);
            float n1 = fmaxf(c1, m1);
            float n2 = fmaxf(c2, m2);

            // Transport: left neighbor's n3 at diag d-1.
            float pm1 = __shfl_up_sync(0xffffffffu, p3, 1);
            if (lane == 0) {
                if (w == 0 || d == 0) {
                    pm1 = TINF;
                } else {
                    unsigned want = (unsigned)(d - 1);
                    unsigned long long got;
                    do {
                        got = *(volatile unsigned long long*)&mb[w - 1][(d - 1) & (DEPTH - 1)];
                    } while ((unsigned)(got >> 32) != want);
                    pm1 = __uint_as_float((unsigned)got);
                }
            }

            float m0 = fminf(fminf(p0, pm1), qm1);
            if ((d | t) == 0) m0 = -TINF;                // seed ca[0][0]=cost[0][0]
            float n0 = fmaxf(c0, m0);

            if (d == NDIAG - 1) res = n3;                // ca[1023][1023] @ t=255

            q0 = p0; q1 = p1; q2 = p2; q3 = p3;
            p0 = n0; p1 = n1; p2 = n2; p3 = n3;
            qm1 = pm1;                                   // d-2 boundary next iter
        }
        if (lane == 31) ((volatile int*)prog)[w] = db + PF - 1;
    }

    if (t == 255) g_bdist[b] = res;
}

// ---------------------------------------------------------------------------
// Kernel 4: mean over batches.
// ---------------------------------------------------------------------------
__global__ void reduce_kernel(float* out) {
    float v = g_bdist[threadIdx.x];
    #pragma unroll
    for (int o = 16; o > 0; o >>= 1) v += __shfl_down_sync(0xffffffffu, v, o);
    if (threadIdx.x == 0) out[0] = v * (1.0f / BB);
}

// ---------------------------------------------------------------------------
extern "C" void kernel_launch(void* const* d_in, const int* in_sizes, int n_in,
                              void* d_out, int out_size) {
    const float* pred = (const float*)d_in[0];
    const float* targ = (const float*)d_in[1];
    (void)in_sizes; (void)n_in; (void)out_size;

    norms_kernel<<<8192, 256>>>(pred, targ);
    dim3 cg(16, 16, 32);
    cost_kernel<<<cg, 256>>>(pred, targ);
    dp_kernel<<<32, 256>>>();
    reduce_kernel<<<1, 32>>>((float*)d_out);
}

// round 4
// speedup vs baseline: 3.5047x; 3.5047x over previous
#include <cuda_runtime.h>
#include <math.h>

#define TINF 3.0e38f
#define TT   1024
#define BB   32
#define DDIM 64
#define RS   1040        // floats per diag row: 8-float TINF guard | 1024 data | 8 tail
#define DROWS 2056       // diag rows per batch (2047 used + prefetch pad)

// Diag-major cost, TINF-padded everywhere cost_kernel doesn't write.
__device__ float g_cost[(size_t)BB * DROWS * RS];
__device__ float g_n2[2 * BB * TT];
__device__ float g_bdist[BB];

// ---------------------------------------------------------------------------
// Kernel 0: fill scratch with +INF (guards, invalid cells, pad rows).
// ---------------------------------------------------------------------------
__global__ void init_kernel() {
    size_t n4 = ((size_t)BB * DROWS * RS) >> 2;
    float4 v = make_float4(TINF, TINF, TINF, TINF);
    float4* p = (float4*)g_cost;
    for (size_t i = blockIdx.x * (size_t)blockDim.x + threadIdx.x; i < n4;
         i += (size_t)gridDim.x * blockDim.x)
        p[i] = v;
}

// ---------------------------------------------------------------------------
// Kernel 1: squared row norms. One warp per 64-dim row.
// ---------------------------------------------------------------------------
__global__ void norms_kernel(const float* __restrict__ pred,
                             const float* __restrict__ targ) {
    int gw   = (blockIdx.x * blockDim.x + threadIdx.x) >> 5;
    int lane = threadIdx.x & 31;
    if (gw >= 2 * BB * TT) return;
    const float* src = (gw < BB * TT) ? (pred + (size_t)gw * DDIM)
                                      : (targ + (size_t)(gw - BB * TT) * DDIM);
    float x0 = src[lane], x1 = src[lane + 32];
    float s = x0 * x0 + x1 * x1;
    #pragma unroll
    for (int o = 16; o > 0; o >>= 1) s += __shfl_down_sync(0xffffffffu, s, o);
    if (lane == 0) g_n2[gw] = s;
}

// ---------------------------------------------------------------------------
// Kernel 2: cost tiles -> diagonal-major valid cells only (rest stays TINF).
// ---------------------------------------------------------------------------
__global__ void __launch_bounds__(256) cost_kernel(const float* __restrict__ pred,
                                                   const float* __restrict__ targ) {
    int jt = blockIdx.x, it = blockIdx.y, b = blockIdx.z;
    int i0 = it * 64, j0 = jt * 64;
    const float* A  = pred + (size_t)b * TT * DDIM;
    const float* Bm = targ + (size_t)b * TT * DDIM;

    __shared__ float sm[8192];
    float* sA = sm;
    float* sB = sm + 4096;

    int tid = threadIdx.x;

    for (int f = tid; f < 1024; f += 256) {
        int r = f >> 4;
        int k4 = (f & 15) * 4;
        float4 va = *(const float4*)(A  + (size_t)(i0 + r) * DDIM + k4);
        sA[(k4 + 0) * 64 + r] = va.x;
        sA[(k4 + 1) * 64 + r] = va.y;
        sA[(k4 + 2) * 64 + r] = va.z;
        sA[(k4 + 3) * 64 + r] = va.w;
        float4 vb = *(const float4*)(Bm + (size_t)(j0 + r) * DDIM + k4);
        sB[(k4 + 0) * 64 + r] = vb.x;
        sB[(k4 + 1) * 64 + r] = vb.y;
        sB[(k4 + 2) * 64 + r] = vb.z;
        sB[(k4 + 3) * 64 + r] = vb.w;
    }
    __syncthreads();

    int tx = tid & 15, ty = tid >> 4;
    float acc[16];
    #pragma unroll
    for (int i = 0; i < 16; ++i) acc[i] = 0.f;

    #pragma unroll 8
    for (int k = 0; k < 64; ++k) {
        float4 a  = *(const float4*)(sA + k * 64 + ty * 4);
        float4 bv = *(const float4*)(sB + k * 64 + tx * 4);
        acc[ 0] += a.x * bv.x;  acc[ 1] += a.x * bv.y;
        acc[ 2] += a.x * bv.z;  acc[ 3] += a.x * bv.w;
        acc[ 4] += a.y * bv.x;  acc[ 5] += a.y * bv.y;
        acc[ 6] += a.y * bv.z;  acc[ 7] += a.y * bv.w;
        acc[ 8] += a.z * bv.x;  acc[ 9] += a.z * bv.y;
        acc[10] += a.z * bv.z;  acc[11] += a.z * bv.w;
        acc[12] += a.w * bv.x;  acc[13] += a.w * bv.y;
        acc[14] += a.w * bv.z;  acc[15] += a.w * bv.w;
    }

    const float* a2p = g_n2 + b * TT;
    const float* b2p = g_n2 + BB * TT + b * TT;
    float a2v[4], b2v[4];
    #pragma unroll
    for (int e = 0; e < 4; ++e) a2v[e] = a2p[i0 + ty * 4 + e];
    #pragma unroll
    for (int f = 0; f < 4; ++f) b2v[f] = b2p[j0 + tx * 4 + f];

    __syncthreads();
    float* Cs = sm;   // reuse, stride 66: diag-gather conflict-free
    #pragma unroll
    for (int e = 0; e < 4; ++e) {
        #pragma unroll
        for (int f = 0; f < 4; ++f) {
            float sq = a2v[e] + b2v[f] - 2.0f * acc[e * 4 + f];
            Cs[(ty * 4 + e) * 66 + (tx * 4 + f)] = sqrtf(fmaxf(sq, 1e-12f));
        }
    }
    __syncthreads();

    float* out = g_cost + (size_t)b * DROWS * RS + 8;   // col-0 base
    int warp = tid >> 5, lane = tid & 31;
    int D0 = i0 + j0;
    for (int dd = warp; dd < 127; dd += 8) {
        int jl = max(0, dd - 63);
        int jh = min(dd, 63);
        int L = jh - jl + 1;
        size_t gb = (size_t)(D0 + dd) * RS + (size_t)(j0 + jl);
        for (int l = lane; l < L; l += 32) {
            int j = jl + l;
            out[gb + l] = Cs[(dd - j) * 66 + j];
        }
    }
}

// ---------------------------------------------------------------------------
// Kernel 3: wavefront DP, 4 diagonals per superstep via redundant halo.
// 256 threads x 4 cols; per superstep each thread computes a 7+6+5+4 cell
// trapezoid, so cross-thread data is exchanged (2 float4 via double-buffered
// smem + one bar.sync) only every 4 diagonals. TINF-padded cost => no masks.
// ---------------------------------------------------------------------------
__device__ __forceinline__ void superstep(
    int db, int t, const float4 ch[4], const float4 co[4],
    float p[4], float q[4],
    float4* spr, float4* sqr, float4* spw, float4* sqw, float& res)
{
    float4 hp4 = spr[t], hq4 = sqr[t];
    if (t == 0) {
        hp4.x = hp4.y = hp4.z = hp4.w = TINF;
        hq4.x = hq4.y = hq4.z = TINF;
        hq4.w = (db == 0) ? -TINF : TINF;   // seed: virtual ca[-1][-1]
    }
    // Extended rows over cols j0-4 .. j0+3 (index i = col - j0 + 4)
    float P[8] = {hp4.x, hp4.y, hp4.z, hp4.w, p[0], p[1], p[2], p[3]};   // diag db-1
    float Q[8] = {hq4.x, hq4.y, hq4.z, hq4.w, q[0], q[1], q[2], q[3]};   // diag db-2
    float CC[4][8];
    #pragma unroll
    for (int k = 0; k < 4; ++k) {
        CC[k][0] = ch[k].x; CC[k][1] = ch[k].y; CC[k][2] = ch[k].z; CC[k][3] = ch[k].w;
        CC[k][4] = co[k].x; CC[k][5] = co[k].y; CC[k][6] = co[k].z; CC[k][7] = co[k].w;
    }
    float A[8], B[8], C[8], D[8];
    #pragma unroll
    for (int i = 1; i < 8; ++i)   // diag db: cols j0-3..j0+3
        A[i] = fmaxf(CC[0][i], fminf(fminf(P[i], P[i-1]), Q[i-1]));
    #pragma unroll
    for (int i = 2; i < 8; ++i)   // diag db+1
        B[i] = fmaxf(CC[1][i], fminf(fminf(A[i], A[i-1]), P[i-1]));
    #pragma unroll
    for (int i = 3; i < 8; ++i)   // diag db+2
        C[i] = fmaxf(CC[2][i], fminf(fminf(B[i], B[i-1]), A[i-1]));
    #pragma unroll
    for (int i = 4; i < 8; ++i)   // diag db+3
        D[i] = fmaxf(CC[3][i], fminf(fminf(C[i], C[i-1]), B[i-1]));

    spw[t + 1] = make_float4(D[4], D[5], D[6], D[7]);
    sqw[t + 1] = make_float4(C[4], C[5], C[6], C[7]);
    if (db == 2044) res = C[7];          // diag 2046, col 1023 @ t=255
    __syncthreads();

    p[0] = D[4]; p[1] = D[5]; p[2] = D[6]; p[3] = D[7];
    q[0] = C[4]; q[1] = C[5]; q[2] = C[6]; q[3] = C[7];
}

__global__ void __launch_bounds__(256, 1) dp_kernel() {
    int b  = blockIdx.x;
    int t  = threadIdx.x;
    int j0 = t << 2;
    const float* SC  = g_cost + (size_t)b * DROWS * RS + 8;   // col-0 base
    const float* SCo = SC + j0;
    const float* SCh = SC + j0 - 4;                            // halo (hits guard @ t=0)

    __shared__ float4 sp[2][257], sq[2][257];
    for (int i = t; i < 2 * 257; i += 256) {
        (&sp[0][0])[i] = make_float4(TINF, TINF, TINF, TINF);
        (&sq[0][0])[i] = make_float4(TINF, TINF, TINF, TINF);
    }
    __syncthreads();

    float p[4] = {TINF, TINF, TINF, TINF};
    float q[4] = {TINF, TINF, TINF, TINF};
    float res = 0.f;

    float4 chA[4], coA[4], chB[4], coB[4];
    #pragma unroll
    for (int k = 0; k < 4; ++k) {
        chA[k] = *(const float4*)(SCh + (size_t)k * RS);
        coA[k] = *(const float4*)(SCo + (size_t)k * RS);
    }

    for (int db = 0; db < 2048; db += 8) {
        #pragma unroll
        for (int k = 0; k < 4; ++k) {     // prefetch superstep db+4
            chB[k] = *(const float4*)(SCh + (size_t)(db + 4 + k) * RS);
            coB[k] = *(const float4*)(SCo + (size_t)(db + 4 + k) * RS);
        }
        superstep(db, t, chA, coA, p, q, sp[0], sq[0], sp[1], sq[1], res);
        #pragma unroll
        for (int k = 0; k < 4; ++k) {     // prefetch superstep db+8 (pad rows at end)
            chA[k] = *(const float4*)(SCh + (size_t)(db + 8 + k) * RS);
            coA[k] = *(const float4*)(SCo + (size_t)(db + 8 + k) * RS);
        }
        superstep(db + 4, t, chB, coB, p, q, sp[1], sq[1], sp[0], sq[0], res);
    }

    if (t == 255) g_bdist[b] = res;
}

// ---------------------------------------------------------------------------
// Kernel 4: mean over batches.
// ---------------------------------------------------------------------------
__global__ void reduce_kernel(float* out) {
    float v = g_bdist[threadIdx.x];
    #pragma unroll
    for (int o = 16; o > 0; o >>= 1) v += __shfl_down_sync(0xffffffffu, v, o);
    if (threadIdx.x == 0) out[0] = v * (1.0f / BB);
}

// ---------------------------------------------------------------------------
extern "C" void kernel_launch(void* const* d_in, const int* in_sizes, int n_in,
                              void* d_out, int out_size) {
    const float* pred = (const float*)d_in[0];
    const float* targ = (const float*)d_in[1];
    (void)in_sizes; (void)n_in; (void)out_size;

    init_kernel<<<2048, 256>>>();
    norms_kernel<<<8192, 256>>>(pred, targ);
    dim3 cg(16, 16, 32);
    cost_kernel<<<cg, 256>>>(pred, targ);
    dp_kernel<<<32, 256>>>();
    reduce_kernel<<<1, 32>>>((float*)d_out);
}

// round 5
// speedup vs baseline: 4.5562x; 1.3000x over previous
#include <cuda_runtime.h>
#include <math.h>

#define TINF 3.0e38f
#define TT   1024
#define BB   32
#define DDIM 64
#define RS   1024        // floats per diag row (128B-aligned rows)
#define DROWS 2072       // 2047 used + prefetch pad (max diag touched = 2071)

// Diag-major cost [b][d][j]. Valid cells written by cost_kernel; invalid cells
// and tail rows pre-filled TINF by init_kernel. 269 MB.
__device__ float g_cost[(size_t)BB * DROWS * RS];
__device__ float g_n2[2 * BB * TT];
__device__ float g_bdist[BB];
__device__ __align__(16) float g_tinf[4] = {3.0e38f, 3.0e38f, 3.0e38f, 3.0e38f};

// ---------------------------------------------------------------------------
// Kernel 0: TINF only where needed — each diag row's invalid region is one
// contiguous run. d<1023: cols d+1..1023; 1024<=d<=2046: cols 0..d-1024;
// d>=2047 (pad rows): full row; d==1023: nothing.
// ---------------------------------------------------------------------------
__global__ void init_kernel() {
    int d = blockIdx.x, b = blockIdx.y;
    float* row = g_cost + ((size_t)b * DROWS + d) * RS;
    int s, e;
    if (d < 1023)        { s = d + 1; e = 1024; }
    else if (d == 1023)  { return; }
    else if (d <= 2046)  { s = 0; e = d - 1023; }
    else                 { s = 0; e = 1024; }
    for (int j = s + threadIdx.x; j < e; j += 256) row[j] = TINF;
}

// ---------------------------------------------------------------------------
// Kernel 1: squared row norms. One warp per 64-dim row.
// ---------------------------------------------------------------------------
__global__ void norms_kernel(const float* __restrict__ pred,
                             const float* __restrict__ targ) {
    int gw   = (blockIdx.x * blockDim.x + threadIdx.x) >> 5;
    int lane = threadIdx.x & 31;
    if (gw >= 2 * BB * TT) return;
    const float* src = (gw < BB * TT) ? (pred + (size_t)gw * DDIM)
                                      : (targ + (size_t)(gw - BB * TT) * DDIM);
    float x0 = src[lane], x1 = src[lane + 32];
    float s = x0 * x0 + x1 * x1;
    #pragma unroll
    for (int o = 16; o > 0; o >>= 1) s += __shfl_down_sync(0xffffffffu, s, o);
    if (lane == 0) g_n2[gw] = s;
}

// ---------------------------------------------------------------------------
// Kernel 2: cost tiles -> diagonal-major valid cells only.
// ---------------------------------------------------------------------------
__global__ void __launch_bounds__(256) cost_kernel(const float* __restrict__ pred,
                                                   const float* __restrict__ targ) {
    int jt = blockIdx.x, it = blockIdx.y, b = blockIdx.z;
    int i0 = it * 64, j0 = jt * 64;
    const float* A  = pred + (size_t)b * TT * DDIM;
    const float* Bm = targ + (size_t)b * TT * DDIM;

    __shared__ float sm[8192];
    float* sA = sm;
    float* sB = sm + 4096;

    int tid = threadIdx.x;

    for (int f = tid; f < 1024; f += 256) {
        int r = f >> 4;
        int k4 = (f & 15) * 4;
        float4 va = *(const float4*)(A  + (size_t)(i0 + r) * DDIM + k4);
        sA[(k4 + 0) * 64 + r] = va.x;
        sA[(k4 + 1) * 64 + r] = va.y;
        sA[(k4 + 2) * 64 + r] = va.z;
        sA[(k4 + 3) * 64 + r] = va.w;
        float4 vb = *(const float4*)(Bm + (size_t)(j0 + r) * DDIM + k4);
        sB[(k4 + 0) * 64 + r] = vb.x;
        sB[(k4 + 1) * 64 + r] = vb.y;
        sB[(k4 + 2) * 64 + r] = vb.z;
        sB[(k4 + 3) * 64 + r] = vb.w;
    }
    __syncthreads();

    int tx = tid & 15, ty = tid >> 4;
    float acc[16];
    #pragma unroll
    for (int i = 0; i < 16; ++i) acc[i] = 0.f;

    #pragma unroll 8
    for (int k = 0; k < 64; ++k) {
        float4 a  = *(const float4*)(sA + k * 64 + ty * 4);
        float4 bv = *(const float4*)(sB + k * 64 + tx * 4);
        acc[ 0] += a.x * bv.x;  acc[ 1] += a.x * bv.y;
        acc[ 2] += a.x * bv.z;  acc[ 3] += a.x * bv.w;
        acc[ 4] += a.y * bv.x;  acc[ 5] += a.y * bv.y;
        acc[ 6] += a.y * bv.z;  acc[ 7] += a.y * bv.w;
        acc[ 8] += a.z * bv.x;  acc[ 9] += a.z * bv.y;
        acc[10] += a.z * bv.z;  acc[11] += a.z * bv.w;
        acc[12] += a.w * bv.x;  acc[13] += a.w * bv.y;
        acc[14] += a.w * bv.z;  acc[15] += a.w * bv.w;
    }

    const float* a2p = g_n2 + b * TT;
    const float* b2p = g_n2 + BB * TT + b * TT;
    float a2v[4], b2v[4];
    #pragma unroll
    for (int e = 0; e < 4; ++e) a2v[e] = a2p[i0 + ty * 4 + e];
    #pragma unroll
    for (int f = 0; f < 4; ++f) b2v[f] = b2p[j0 + tx * 4 + f];

    __syncthreads();
    float* Cs = sm;   // reuse, stride 66: diag-gather conflict-free
    #pragma unroll
    for (int e = 0; e < 4; ++e) {
        #pragma unroll
        for (int f = 0; f < 4; ++f) {
            float sq = a2v[e] + b2v[f] - 2.0f * acc[e * 4 + f];
            Cs[(ty * 4 + e) * 66 + (tx * 4 + f)] = sqrtf(fmaxf(sq, 1e-12f));
        }
    }
    __syncthreads();

    float* out = g_cost + (size_t)b * DROWS * RS;
    int warp = tid >> 5, lane = tid & 31;
    int D0 = i0 + j0;
    for (int dd = warp; dd < 127; dd += 8) {
        int jl = max(0, dd - 63);
        int jh = min(dd, 63);
        int L = jh - jl + 1;
        size_t gb = (size_t)(D0 + dd) * RS + (size_t)(j0 + jl);
        for (int l = lane; l < L; l += 32) {
            int j = jl + l;
            out[gb + l] = Cs[(dd - j) * 66 + j];
        }
    }
}

// ---------------------------------------------------------------------------
// Kernel 3: wavefront DP, 4 diagonals per superstep via redundant halo,
// cost prefetched TWO supersteps ahead through a 3-deep register ring
// (all indices static under the 6-superstep unroll).
// ---------------------------------------------------------------------------
__device__ __forceinline__ void superstep(
    int db, int t, const float4 ch[4], const float4 co[4],
    float p[4], float q[4],
    float4* spr, float4* sqr, float4* spw, float4* sqw, float& res)
{
    float4 hp4 = spr[t], hq4 = sqr[t];
    if (t == 0) {
        hp4.x = hp4.y = hp4.z = hp4.w = TINF;
        hq4.x = hq4.y = hq4.z = TINF;
        hq4.w = (db == 0) ? -TINF : TINF;   // seed: virtual ca[-1][-1]
    }
    float P[8] = {hp4.x, hp4.y, hp4.z, hp4.w, p[0], p[1], p[2], p[3]};   // diag db-1
    float Q[8] = {hq4.x, hq4.y, hq4.z, hq4.w, q[0], q[1], q[2], q[3]};   // diag db-2
    float CC[4][8];
    #pragma unroll
    for (int k = 0; k < 4; ++k) {
        CC[k][0] = ch[k].x; CC[k][1] = ch[k].y; CC[k][2] = ch[k].z; CC[k][3] = ch[k].w;
        CC[k][4] = co[k].x; CC[k][5] = co[k].y; CC[k][6] = co[k].z; CC[k][7] = co[k].w;
    }
    float A[8], B[8], C[8], D[8];
    #pragma unroll
    for (int i = 1; i < 8; ++i)
        A[i] = fmaxf(CC[0][i], fminf(fminf(P[i], P[i-1]), Q[i-1]));
    #pragma unroll
    for (int i = 2; i < 8; ++i)
        B[i] = fmaxf(CC[1][i], fminf(fminf(A[i], A[i-1]), P[i-1]));
    #pragma unroll
    for (int i = 3; i < 8; ++i)
        C[i] = fmaxf(CC[2][i], fminf(fminf(B[i], B[i-1]), A[i-1]));
    #pragma unroll
    for (int i = 4; i < 8; ++i)
        D[i] = fmaxf(CC[3][i], fminf(fminf(C[i], C[i-1]), B[i-1]));

    spw[t + 1] = make_float4(D[4], D[5], D[6], D[7]);
    sqw[t + 1] = make_float4(C[4], C[5], C[6], C[7]);
    if (db == 2044) res = C[7];          // diag 2046, col 1023 @ t=255
    __syncthreads();

    p[0] = D[4]; p[1] = D[5]; p[2] = D[6]; p[3] = D[7];
    q[0] = C[4]; q[1] = C[5]; q[2] = C[6]; q[3] = C[7];
}

__global__ void __launch_bounds__(256, 1) dp_kernel() {
    int b  = blockIdx.x;
    int t  = threadIdx.x;
    int j0 = t << 2;
    const float* SCo = g_cost + (size_t)b * DROWS * RS + j0;
    // Halo: thread t reads cols j0-4..j0-1; t==0 reads a static TINF quad
    // via a stride-0 pointer (no guard columns, no per-iteration branch).
    const float*  SCh  = (t == 0) ? g_tinf : (SCo - 4);
    const size_t  HST  = (t == 0) ? 0 : (size_t)RS;

    __shared__ float4 sp[2][257], sq[2][257];
    for (int i = t; i < 2 * 257; i += 256) {
        (&sp[0][0])[i] = make_float4(TINF, TINF, TINF, TINF);
        (&sq[0][0])[i] = make_float4(TINF, TINF, TINF, TINF);
    }
    __syncthreads();

    float p[4] = {TINF, TINF, TINF, TINF};
    float q[4] = {TINF, TINF, TINF, TINF};
    float res = 0.f;

    // 3-deep cost ring: buffer u%3 holds superstep (diag base db+4u)'s rows.
    float4 CH[3][4], CO[3][4];
    #pragma unroll
    for (int k = 0; k < 4; ++k) {
        CH[0][k] = *(const float4*)(SCh + (size_t)(k)     * HST);
        CO[0][k] = *(const float4*)(SCo + (size_t)(k)     * RS);
        CH[1][k] = *(const float4*)(SCh + (size_t)(4 + k) * HST);
        CO[1][k] = *(const float4*)(SCo + (size_t)(4 + k) * RS);
    }

    // 2064 diagonals = 86 outer iters x 6 supersteps (ring idx u%3 and
    // sp/sq parity u%2 both static). Max diag prefetched = 2040+20+8+3 = 2071.
    for (int db = 0; db < 2064; db += 24) {
        #pragma unroll
        for (int u = 0; u < 6; ++u) {
            const int cur = u % 3;           // buffer being consumed
            const int pre = (u + 2) % 3;     // buffer to refill (superstep u+2)
            int dpre = db + 4 * u + 8;
            #pragma unroll
            for (int k = 0; k < 4; ++k) {
                CH[pre][k] = *(const float4*)(SCh + (size_t)(dpre + k) * HST);
                CO[pre][k] = *(const float4*)(SCo + (size_t)(dpre + k) * RS);
            }
            if (u % 2 == 0)
                superstep(db + 4 * u, t, CH[cur], CO[cur], p, q,
                          &sp[0][0], &sq[0][0], &sp[1][0], &sq[1][0], res);
            else
                superstep(db + 4 * u, t, CH[cur], CO[cur], p, q,
                          &sp[1][0], &sq[1][0], &sp[0][0], &sq[0][0], res);
        }
    }

    if (t == 255) g_bdist[b] = res;
}

// ---------------------------------------------------------------------------
// Kernel 4: mean over batches.
// ---------------------------------------------------------------------------
__global__ void reduce_kernel(float* out) {
    float v = g_bdist[threadIdx.x];
    #pragma unroll
    for (int o = 16; o > 0; o >>= 1) v += __shfl_down_sync(0xffffffffu, v, o);
    if (threadIdx.x == 0) out[0] = v * (1.0f / BB);
}

// ---------------------------------------------------------------------------
extern "C" void kernel_launch(void* const* d_in, const int* in_sizes, int n_in,
                              void* d_out, int out_size) {
    const float* pred = (const float*)d_in[0];
    const float* targ = (const float*)d_in[1];
    (void)in_sizes; (void)n_in; (void)out_size;

    dim3 ig(DROWS, BB);
    init_kernel<<<ig, 256>>>();
    norms_kernel<<<8192, 256>>>(pred, targ);
    dim3 cg(16, 16, 32);
    cost_kernel<<<cg, 256>>>(pred, targ);
    dp_kernel<<<32, 256>>>();
    reduce_kernel<<<1, 32>>>((float*)d_out);
}

// round 6
// speedup vs baseline: 4.9817x; 1.0934x over previous
#include <cuda_runtime.h>
#include <math.h>

#define TINF 3.0e38f
#define TT   1024
#define BB   32
#define DDIM 64
#define RS   1024        // floats per diag row (128B-aligned rows)
#define DROWS 2072       // 2047 used + prefetch pad (max diag touched = 2071)

// Diag-major cost [b][d][j]. Valid cells written by cost_kernel; invalid cells
// and tail rows pre-filled TINF by init_kernel. 269 MB.
__device__ float g_cost[(size_t)BB * DROWS * RS];
__device__ float g_n2[2 * BB * TT];
__device__ float g_bdist[BB];
__device__ __align__(16) float g_tinf[4] = {3.0e38f, 3.0e38f, 3.0e38f, 3.0e38f};

// ---------------------------------------------------------------------------
// Kernel 0: TINF only where needed — each diag row's invalid region is one
// contiguous run. d<1023: cols d+1..1023; 1024<=d<=2046: cols 0..d-1024;
// d>=2047 (pad rows): full row; d==1023: nothing.
// ---------------------------------------------------------------------------
__global__ void init_kernel() {
    int d = blockIdx.x, b = blockIdx.y;
    float* row = g_cost + ((size_t)b * DROWS + d) * RS;
    int s, e;
    if (d < 1023)        { s = d + 1; e = 1024; }
    else if (d == 1023)  { return; }
    else if (d <= 2046)  { s = 0; e = d - 1023; }
    else                 { s = 0; e = 1024; }
    for (int j = s + threadIdx.x; j < e; j += 256) row[j] = TINF;
}

// ---------------------------------------------------------------------------
// Kernel 1: squared row norms. One warp per 64-dim row.
// ---------------------------------------------------------------------------
__global__ void norms_kernel(const float* __restrict__ pred,
                             const float* __restrict__ targ) {
    int gw   = (blockIdx.x * blockDim.x + threadIdx.x) >> 5;
    int lane = threadIdx.x & 31;
    if (gw >= 2 * BB * TT) return;
    const float* src = (gw < BB * TT) ? (pred + (size_t)gw * DDIM)
                                      : (targ + (size_t)(gw - BB * TT) * DDIM);
    float x0 = src[lane], x1 = src[lane + 32];
    float s = x0 * x0 + x1 * x1;
    #pragma unroll
    for (int o = 16; o > 0; o >>= 1) s += __shfl_down_sync(0xffffffffu, s, o);
    if (lane == 0) g_n2[gw] = s;
}

// ---------------------------------------------------------------------------
// Kernel 2: cost tiles, 128x128 per block, 8x8 microtile (16x16 threads),
// k-chunked smem (BK=16) with register prefetch. Epilogue stages 64x64
// quadrants in smem and writes diagonal-major runs (coalesced).
// ---------------------------------------------------------------------------
__global__ void __launch_bounds__(256, 2) cost_kernel(const float* __restrict__ pred,
                                                      const float* __restrict__ targ) {
    int b  = blockIdx.z;
    int i0 = blockIdx.y * 128, j0 = blockIdx.x * 128;
    const float* A  = pred + (size_t)b * TT * DDIM;
    const float* Bm = targ + (size_t)b * TT * DDIM;

    __shared__ float sA[16 * 128];   // sA[k][row]
    __shared__ float sB[16 * 128];   // sB[k][col]
    __shared__ float Cs[64 * 64];    // quadrant staging (stride 64: diag reads conflict-free)

    int tid = threadIdx.x;
    int tx = tid & 15, ty = tid >> 4;
    int lr = tid & 127;              // tile row/col for loads
    int lk = (tid >> 7) * 8;         // k-offset within chunk: 0 or 8

    const float* ga = A  + (size_t)(i0 + lr) * DDIM + lk;
    const float* gb = Bm + (size_t)(j0 + lr) * DDIM + lk;

    float4 ra0 = *(const float4*)(ga);
    float4 ra1 = *(const float4*)(ga + 4);
    float4 rb0 = *(const float4*)(gb);
    float4 rb1 = *(const float4*)(gb + 4);

    float acc[64];
    #pragma unroll
    for (int i = 0; i < 64; ++i) acc[i] = 0.f;

    #pragma unroll 1
    for (int kc = 0; kc < 64; kc += 16) {
        // Store prefetched chunk to smem transposed (lr consecutive -> conflict-free STS)
        sA[(lk + 0) * 128 + lr] = ra0.x;  sA[(lk + 1) * 128 + lr] = ra0.y;
        sA[(lk + 2) * 128 + lr] = ra0.z;  sA[(lk + 3) * 128 + lr] = ra0.w;
        sA[(lk + 4) * 128 + lr] = ra1.x;  sA[(lk + 5) * 128 + lr] = ra1.y;
        sA[(lk + 6) * 128 + lr] = ra1.z;  sA[(lk + 7) * 128 + lr] = ra1.w;
        sB[(lk + 0) * 128 + lr] = rb0.x;  sB[(lk + 1) * 128 + lr] = rb0.y;
        sB[(lk + 2) * 128 + lr] = rb0.z;  sB[(lk + 3) * 128 + lr] = rb0.w;
        sB[(lk + 4) * 128 + lr] = rb1.x;  sB[(lk + 5) * 128 + lr] = rb1.y;
        sB[(lk + 6) * 128 + lr] = rb1.z;  sB[(lk + 7) * 128 + lr] = rb1.w;
        __syncthreads();

        if (kc < 48) {                       // prefetch next chunk
            ra0 = *(const float4*)(ga + kc + 16);
            ra1 = *(const float4*)(ga + kc + 20);
            rb0 = *(const float4*)(gb + kc + 16);
            rb1 = *(const float4*)(gb + kc + 20);
        }

        #pragma unroll
        for (int kk = 0; kk < 16; ++kk) {
            float4 av0 = *(const float4*)(sA + kk * 128 + ty * 8);
            float4 av1 = *(const float4*)(sA + kk * 128 + ty * 8 + 4);
            float4 bv0 = *(const float4*)(sB + kk * 128 + tx * 8);
            float4 bv1 = *(const float4*)(sB + kk * 128 + tx * 8 + 4);
            float av[8] = {av0.x, av0.y, av0.z, av0.w, av1.x, av1.y, av1.z, av1.w};
            float bv[8] = {bv0.x, bv0.y, bv0.z, bv0.w, bv1.x, bv1.y, bv1.z, bv1.w};
            #pragma unroll
            for (int e = 0; e < 8; ++e)
                #pragma unroll
                for (int f = 0; f < 8; ++f)
                    acc[e * 8 + f] += av[e] * bv[f];
        }
        __syncthreads();
    }

    // Row norms for this thread's 8x8 microtile
    const float* a2p = g_n2 + b * TT + i0 + ty * 8;
    const float* b2p = g_n2 + BB * TT + b * TT + j0 + tx * 8;
    float a2v[8], b2v[8];
    #pragma unroll
    for (int e = 0; e < 8; ++e) { a2v[e] = a2p[e]; b2v[e] = b2p[e]; }

    // Epilogue: 4 quadrants of 64x64. Each thread's microtile lies wholly in
    // quadrant (ty>>3, tx>>3).
    int qi = ty >> 3, qj = tx >> 3;
    int tyq = ty & 7, txq = tx & 7;
    float* out = g_cost + (size_t)b * DROWS * RS;
    int warp = tid >> 5, lane = tid & 31;

    #pragma unroll 1
    for (int qq = 0; qq < 4; ++qq) {
        __syncthreads();                     // Cs free (previous drain done)
        if (qi == (qq >> 1) && qj == (qq & 1)) {
            #pragma unroll
            for (int e = 0; e < 8; ++e)
                #pragma unroll
                for (int f = 0; f < 8; ++f) {
                    float sq = a2v[e] + b2v[f] - 2.0f * acc[e * 8 + f];
                    Cs[(tyq * 8 + e) * 64 + txq * 8 + f] = sqrtf(fmaxf(sq, 1e-12f));
                }
        }
        __syncthreads();

        int i0q = i0 + (qq >> 1) * 64, j0q = j0 + (qq & 1) * 64;
        int D0 = i0q + j0q;
        for (int dd = warp; dd < 127; dd += 8) {
            int jl = max(0, dd - 63);
            int jh = min(dd, 63);
            int L = jh - jl + 1;
            size_t gbase = (size_t)(D0 + dd) * RS + (size_t)(j0q + jl);
            for (int l = lane; l < L; l += 32) {
                int j = jl + l;
                out[gbase + l] = Cs[(dd - j) * 64 + j];
            }
        }
    }
}

// ---------------------------------------------------------------------------
// Kernel 3: wavefront DP, 4 diagonals per superstep via redundant halo,
// cost prefetched TWO supersteps ahead through a 3-deep register ring
// (all indices static under the 6-superstep unroll).
// ---------------------------------------------------------------------------
__device__ __forceinline__ void superstep(
    int db, int t, const float4 ch[4], const float4 co[4],
    float p[4], float q[4],
    float4* spr, float4* sqr, float4* spw, float4* sqw, float& res)
{
    float4 hp4 = spr[t], hq4 = sqr[t];
    if (t == 0) {
        hp4.x = hp4.y = hp4.z = hp4.w = TINF;
        hq4.x = hq4.y = hq4.z = TINF;
        hq4.w = (db == 0) ? -TINF : TINF;   // seed: virtual ca[-1][-1]
    }
    float P[8] = {hp4.x, hp4.y, hp4.z, hp4.w, p[0], p[1], p[2], p[3]};   // diag db-1
    float Q[8] = {hq4.x, hq4.y, hq4.z, hq4.w, q[0], q[1], q[2], q[3]};   // diag db-2
    float CC[4][8];
    #pragma unroll
    for (int k = 0; k < 4; ++k) {
        CC[k][0] = ch[k].x; CC[k][1] = ch[k].y; CC[k][2] = ch[k].z; CC[k][3] = ch[k].w;
        CC[k][4] = co[k].x; CC[k][5] = co[k].y; CC[k][6] = co[k].z; CC[k][7] = co[k].w;
    }
    float A[8], B[8], C[8], D[8];
    #pragma unroll
    for (int i = 1; i < 8; ++i)
        A[i] = fmaxf(CC[0][i], fminf(fminf(P[i], P[i-1]), Q[i-1]));
    #pragma unroll
    for (int i = 2; i < 8; ++i)
        B[i] = fmaxf(CC[1][i], fminf(fminf(A[i], A[i-1]), P[i-1]));
    #pragma unroll
    for (int i = 3; i < 8; ++i)
        C[i] = fmaxf(CC[2][i], fminf(fminf(B[i], B[i-1]), A[i-1]));
    #pragma unroll
    for (int i = 4; i < 8; ++i)
        D[i] = fmaxf(CC[3][i], fminf(fminf(C[i], C[i-1]), B[i-1]));

    spw[t + 1] = make_float4(D[4], D[5], D[6], D[7]);
    sqw[t + 1] = make_float4(C[4], C[5], C[6], C[7]);
    if (db == 2044) res = C[7];          // diag 2046, col 1023 @ t=255
    __syncthreads();

    p[0] = D[4]; p[1] = D[5]; p[2] = D[6]; p[3] = D[7];
    q[0] = C[4]; q[1] = C[5]; q[2] = C[6]; q[3] = C[7];
}

__global__ void __launch_bounds__(256, 1) dp_kernel() {
    int b  = blockIdx.x;
    int t  = threadIdx.x;
    int j0 = t << 2;
    const float* SCo = g_cost + (size_t)b * DROWS * RS + j0;
    const float*  SCh  = (t == 0) ? g_tinf : (SCo - 4);
    const size_t  HST  = (t == 0) ? 0 : (size_t)RS;

    __shared__ float4 sp[2][257], sq[2][257];
    for (int i = t; i < 2 * 257; i += 256) {
        (&sp[0][0])[i] = make_float4(TINF, TINF, TINF, TINF);
        (&sq[0][0])[i] = make_float4(TINF, TINF, TINF, TINF);
    }
    __syncthreads();

    float p[4] = {TINF, TINF, TINF, TINF};
    float q[4] = {TINF, TINF, TINF, TINF};
    float res = 0.f;

    float4 CH[3][4], CO[3][4];
    #pragma unroll
    for (int k = 0; k < 4; ++k) {
        CH[0][k] = *(const float4*)(SCh + (size_t)(k)     * HST);
        CO[0][k] = *(const float4*)(SCo + (size_t)(k)     * RS);
        CH[1][k] = *(const float4*)(SCh + (size_t)(4 + k) * HST);
        CO[1][k] = *(const float4*)(SCo + (size_t)(4 + k) * RS);
    }

    for (int db = 0; db < 2064; db += 24) {
        #pragma unroll
        for (int u = 0; u < 6; ++u) {
            const int cur = u % 3;
            const int pre = (u + 2) % 3;
            int dpre = db + 4 * u + 8;
            #pragma unroll
            for (int k = 0; k < 4; ++k) {
                CH[pre][k] = *(const float4*)(SCh + (size_t)(dpre + k) * HST);
                CO[pre][k] = *(const float4*)(SCo + (size_t)(dpre + k) * RS);
            }
            if (u % 2 == 0)
                superstep(db + 4 * u, t, CH[cur], CO[cur], p, q,
                          &sp[0][0], &sq[0][0], &sp[1][0], &sq[1][0], res);
            else
                superstep(db + 4 * u, t, CH[cur], CO[cur], p, q,
                          &sp[1][0], &sq[1][0], &sp[0][0], &sq[0][0], res);
        }
    }

    if (t == 255) g_bdist[b] = res;
}

// ---------------------------------------------------------------------------
// Kernel 4: mean over batches.
// ---------------------------------------------------------------------------
__global__ void reduce_kernel(float* out) {
    float v = g_bdist[threadIdx.x];
    #pragma unroll
    for (int o = 16; o > 0; o >>= 1) v += __shfl_down_sync(0xffffffffu, v, o);
    if (threadIdx.x == 0) out[0] = v * (1.0f / BB);
}

// ---------------------------------------------------------------------------
extern "C" void kernel_launch(void* const* d_in, const int* in_sizes, int n_in,
                              void* d_out, int out_size) {
    const float* pred = (const float*)d_in[0];
    const float* targ = (const float*)d_in[1];
    (void)in_sizes; (void)n_in; (void)out_size;

    dim3 ig(DROWS, BB);
    init_kernel<<<ig, 256>>>();
    norms_kernel<<<8192, 256>>>(pred, targ);
    dim3 cg(8, 8, 32);
    cost_kernel<<<cg, 256>>>(pred, targ);
    dp_kernel<<<32, 256>>>();
    reduce_kernel<<<1, 32>>>((float*)d_out);
}

// round 7
// speedup vs baseline: 5.7832x; 1.1609x over previous
#include <cuda_runtime.h>
#include <math.h>

#define TINF 3.0e38f
#define TT   1024
#define BB   32
#define DDIM 64
#define RS   1024        // floats per diag row (128B-aligned rows)
#define DROWS 2072       // 2047 used + prefetch pad (max diag touched = 2071)

// Diag-major cost [b][d][j]. Valid cells written by cost_kernel; invalid cells
// and tail rows pre-filled TINF by init_kernel. 269 MB.
__device__ float g_cost[(size_t)BB * DROWS * RS];
__device__ float g_n2[2 * BB * TT];
__device__ float g_bdist[BB];
__device__ __align__(16) float g_tinf[4] = {3.0e38f, 3.0e38f, 3.0e38f, 3.0e38f};

// ---------------------------------------------------------------------------
// Kernel 0: TINF only where needed — each diag row's invalid region is one
// contiguous run.
// ---------------------------------------------------------------------------
__global__ void init_kernel() {
    int d = blockIdx.x, b = blockIdx.y;
    float* row = g_cost + ((size_t)b * DROWS + d) * RS;
    int s, e;
    if (d < 1023)        { s = d + 1; e = 1024; }
    else if (d == 1023)  { return; }
    else if (d <= 2046)  { s = 0; e = d - 1023; }
    else                 { s = 0; e = 1024; }
    for (int j = s + threadIdx.x; j < e; j += 256) row[j] = TINF;
}

// ---------------------------------------------------------------------------
// Kernel 1: squared row norms. One warp per 64-dim row.
// ---------------------------------------------------------------------------
__global__ void norms_kernel(const float* __restrict__ pred,
                             const float* __restrict__ targ) {
    int gw   = (blockIdx.x * blockDim.x + threadIdx.x) >> 5;
    int lane = threadIdx.x & 31;
    if (gw >= 2 * BB * TT) return;
    const float* src = (gw < BB * TT) ? (pred + (size_t)gw * DDIM)
                                      : (targ + (size_t)(gw - BB * TT) * DDIM);
    float x0 = src[lane], x1 = src[lane + 32];
    float s = x0 * x0 + x1 * x1;
    #pragma unroll
    for (int o = 16; o > 0; o >>= 1) s += __shfl_down_sync(0xffffffffu, s, o);
    if (lane == 0) g_n2[gw] = s;
}

// ---------------------------------------------------------------------------
// Kernel 2: TF32 tensor-core cost tiles. 128x128 per block, 8 warps in a 4x2
// grid; each warp computes 32x64 via m16n8k8 tf32 mma. Padded-stride-36 smem
// makes A/B fragment gathers bank-conflict-free (bank = 4*group + tig).
// Epilogue stages 64x64 quadrants (stride 66) and writes diag-major runs.
// ---------------------------------------------------------------------------
__device__ __forceinline__ unsigned f2tf(float x) {
    unsigned u;
    asm("cvt.rna.tf32.f32 %0, %1;" : "=r"(u) : "f"(x));
    return u;
}
__device__ __forceinline__ void mma_tf32(float c[4], const unsigned a[4],
                                         const unsigned b[2]) {
    asm volatile(
        "mma.sync.aligned.m16n8k8.row.col.f32.tf32.tf32.f32 "
        "{%0,%1,%2,%3}, {%4,%5,%6,%7}, {%8,%9}, {%0,%1,%2,%3};"
        : "+f"(c[0]), "+f"(c[1]), "+f"(c[2]), "+f"(c[3])
        : "r"(a[0]), "r"(a[1]), "r"(a[2]), "r"(a[3]), "r"(b[0]), "r"(b[1]));
}

#define SKP 36   // smem k-stride (32 + 4 pad)

__global__ void __launch_bounds__(256, 2) cost_kernel(const float* __restrict__ pred,
                                                      const float* __restrict__ targ) {
    int b  = blockIdx.z;
    int i0 = blockIdx.y * 128, j0 = blockIdx.x * 128;
    const float* A  = pred + (size_t)b * TT * DDIM;
    const float* Bm = targ + (size_t)b * TT * DDIM;

    __shared__ __align__(16) float smbuf[2 * 128 * SKP];   // 36864 B
    float* sA = smbuf;
    float* sB = smbuf + 128 * SKP;
    float* Cs = smbuf;                                     // reused in epilogue

    int tid  = threadIdx.x;
    int lane = tid & 31, w = tid >> 5;
    int g    = lane >> 2, tig = lane & 3;
    int wm   = (w & 3) * 32, wn = (w >> 2) * 64;

    float c[2][8][4];
    #pragma unroll
    for (int mt = 0; mt < 2; ++mt)
        #pragma unroll
        for (int nt = 0; nt < 8; ++nt)
            #pragma unroll
            for (int e = 0; e < 4; ++e) c[mt][nt][e] = 0.f;

    int lr = tid >> 1;                 // tile row 0..127
    int lk = (tid & 1) * 16;           // k-offset 0 or 16 within 32-chunk
    const float* ga = A  + (size_t)(i0 + lr) * DDIM + lk;
    const float* gb = Bm + (size_t)(j0 + lr) * DDIM + lk;

    #pragma unroll 1
    for (int kc = 0; kc < 64; kc += 32) {
        #pragma unroll
        for (int c4 = 0; c4 < 4; ++c4) {
            float4 va = *(const float4*)(ga + kc + c4 * 4);
            float4 vb = *(const float4*)(gb + kc + c4 * 4);
            int o = lr * SKP + lk + c4 * 4;
            sA[o + 0] = __uint_as_float(f2tf(va.x));
            sA[o + 1] = __uint_as_float(f2tf(va.y));
            sA[o + 2] = __uint_as_float(f2tf(va.z));
            sA[o + 3] = __uint_as_float(f2tf(va.w));
            sB[o + 0] = __uint_as_float(f2tf(vb.x));
            sB[o + 1] = __uint_as_float(f2tf(vb.y));
            sB[o + 2] = __uint_as_float(f2tf(vb.z));
            sB[o + 3] = __uint_as_float(f2tf(vb.w));
        }
        __syncthreads();

        #pragma unroll
        for (int ks = 0; ks < 32; ks += 8) {
            unsigned af[2][4], bf[8][2];
            #pragma unroll
            for (int mt = 0; mt < 2; ++mt) {
                int mr = wm + mt * 16;
                af[mt][0] = __float_as_uint(sA[(mr + g)     * SKP + ks + tig]);
                af[mt][1] = __float_as_uint(sA[(mr + g + 8) * SKP + ks + tig]);
                af[mt][2] = __float_as_uint(sA[(mr + g)     * SKP + ks + tig + 4]);
                af[mt][3] = __float_as_uint(sA[(mr + g + 8) * SKP + ks + tig + 4]);
            }
            #pragma unroll
            for (int nt = 0; nt < 8; ++nt) {
                int nr = wn + nt * 8 + g;
                bf[nt][0] = __float_as_uint(sB[nr * SKP + ks + tig]);
                bf[nt][1] = __float_as_uint(sB[nr * SKP + ks + tig + 4]);
            }
            #pragma unroll
            for (int mt = 0; mt < 2; ++mt)
                #pragma unroll
                for (int nt = 0; nt < 8; ++nt)
                    mma_tf32(c[mt][nt], af[mt], bf[nt]);
        }
        __syncthreads();
    }

    // Norms for this thread's fragment rows/cols
    float a2v[2][2], b2v[8][2];
    #pragma unroll
    for (int mt = 0; mt < 2; ++mt) {
        a2v[mt][0] = g_n2[b * TT + i0 + wm + mt * 16 + g];
        a2v[mt][1] = g_n2[b * TT + i0 + wm + mt * 16 + g + 8];
    }
    #pragma unroll
    for (int nt = 0; nt < 8; ++nt) {
        b2v[nt][0] = g_n2[BB * TT + b * TT + j0 + wn + nt * 8 + 2 * tig];
        b2v[nt][1] = g_n2[BB * TT + b * TT + j0 + wn + nt * 8 + 2 * tig + 1];
    }

    float* out = g_cost + (size_t)b * DROWS * RS;

    #pragma unroll 1
    for (int qq = 0; qq < 4; ++qq) {
        int qi = qq >> 1, qj = qq & 1;
        __syncthreads();                     // Cs free (prev drain / GEMM done)
        if ((w >> 2) == qj && ((w & 3) >> 1) == qi) {
            int mloc0 = ((w & 3) & 1) * 32;
            #pragma unroll
            for (int mt = 0; mt < 2; ++mt) {
                int ml = mloc0 + mt * 16 + g;
                #pragma unroll
                for (int nt = 0; nt < 8; ++nt) {
                    int nl = nt * 8 + 2 * tig;
                    float s0 = a2v[mt][0] + b2v[nt][0] - 2.0f * c[mt][nt][0];
                    float s1 = a2v[mt][0] + b2v[nt][1] - 2.0f * c[mt][nt][1];
                    float s2 = a2v[mt][1] + b2v[nt][0] - 2.0f * c[mt][nt][2];
                    float s3 = a2v[mt][1] + b2v[nt][1] - 2.0f * c[mt][nt][3];
                    Cs[ml * 66 + nl]           = sqrtf(fmaxf(s0, 1e-12f));
                    Cs[ml * 66 + nl + 1]       = sqrtf(fmaxf(s1, 1e-12f));
                    Cs[(ml + 8) * 66 + nl]     = sqrtf(fmaxf(s2, 1e-12f));
                    Cs[(ml + 8) * 66 + nl + 1] = sqrtf(fmaxf(s3, 1e-12f));
                }
            }
        }
        __syncthreads();

        int i0q = i0 + qi * 64, j0q = j0 + qj * 64;
        int D0 = i0q + j0q;
        for (int dd = w; dd < 127; dd += 8) {
            int jl = max(0, dd - 63);
            int jh = min(dd, 63);
            int L = jh - jl + 1;
            size_t gbase = (size_t)(D0 + dd) * RS + (size_t)(j0q + jl);
            for (int l = lane; l < L; l += 32) {
                int j = jl + l;
                out[gbase + l] = Cs[(dd - j) * 66 + j];
            }
        }
    }
}

// ---------------------------------------------------------------------------
// Kernel 3: wavefront DP, 4 diagonals per superstep via redundant halo.
// Halo cost = left neighbor's CO quad: lanes 1-31 get it via shfl_up (no LDG);
// only lane 0 of each warp keeps a (1-sector) halo load ring.
// ---------------------------------------------------------------------------
__device__ __forceinline__ void superstep(
    int db, int t, int lane, const float4 co[4], const float4 chl[4],
    float p[4], float q[4],
    float4* spr, float4* sqr, float4* spw, float4* sqw, float& res)
{
    float4 hp4 = spr[t], hq4 = sqr[t];
    if (t == 0) {
        hp4.x = hp4.y = hp4.z = hp4.w = TINF;
        hq4.x = hq4.y = hq4.z = TINF;
        hq4.w = (db == 0) ? -TINF : TINF;   // seed: virtual ca[-1][-1]
    }
    float P[8] = {hp4.x, hp4.y, hp4.z, hp4.w, p[0], p[1], p[2], p[3]};   // diag db-1
    float Q[8] = {hq4.x, hq4.y, hq4.z, hq4.w, q[0], q[1], q[2], q[3]};   // diag db-2
    float CC[4][8];
    #pragma unroll
    for (int k = 0; k < 4; ++k) {
        float sx = __shfl_up_sync(0xffffffffu, co[k].x, 1);
        float sy = __shfl_up_sync(0xffffffffu, co[k].y, 1);
        float sz = __shfl_up_sync(0xffffffffu, co[k].z, 1);
        float sw = __shfl_up_sync(0xffffffffu, co[k].w, 1);
        CC[k][0] = lane ? sx : chl[k].x;
        CC[k][1] = lane ? sy : chl[k].y;
        CC[k][2] = lane ? sz : chl[k].z;
        CC[k][3] = lane ? sw : chl[k].w;
        CC[k][4] = co[k].x; CC[k][5] = co[k].y;
        CC[k][6] = co[k].z; CC[k][7] = co[k].w;
    }
    float A[8], B[8], C[8], D[8];
    #pragma unroll
    for (int i = 1; i < 8; ++i)
        A[i] = fmaxf(CC[0][i], fminf(fminf(P[i], P[i-1]), Q[i-1]));
    #pragma unroll
    for (int i = 2; i < 8; ++i)
        B[i] = fmaxf(CC[1][i], fminf(fminf(A[i], A[i-1]), P[i-1]));
    #pragma unroll
    for (int i = 3; i < 8; ++i)
        C[i] = fmaxf(CC[2][i], fminf(fminf(B[i], B[i-1]), A[i-1]));
    #pragma unroll
    for (int i = 4; i < 8; ++i)
        D[i] = fmaxf(CC[3][i], fminf(fminf(C[i], C[i-1]), B[i-1]));

    spw[t + 1] = make_float4(D[4], D[5], D[6], D[7]);
    sqw[t + 1] = make_float4(C[4], C[5], C[6], C[7]);
    if (db == 2044) res = C[7];          // diag 2046, col 1023 @ t=255
    __syncthreads();

    p[0] = D[4]; p[1] = D[5]; p[2] = D[6]; p[3] = D[7];
    q[0] = C[4]; q[1] = C[5]; q[2] = C[6]; q[3] = C[7];
}

__global__ void __launch_bounds__(256, 1) dp_kernel() {
    int b    = blockIdx.x;
    int t    = threadIdx.x;
    int lane = t & 31;
    int j0   = t << 2;
    const float* SCo = g_cost + (size_t)b * DROWS * RS + j0;
    const float* SCh = (t == 0) ? g_tinf : (SCo - 4);   // lane-0 halo base
    const size_t HST = (t == 0) ? 0 : (size_t)RS;

    __shared__ float4 sp[2][257], sq[2][257];
    for (int i = t; i < 2 * 257; i += 256) {
        (&sp[0][0])[i] = make_float4(TINF, TINF, TINF, TINF);
        (&sq[0][0])[i] = make_float4(TINF, TINF, TINF, TINF);
    }
    __syncthreads();

    float p[4] = {TINF, TINF, TINF, TINF};
    float q[4] = {TINF, TINF, TINF, TINF};
    float res = 0.f;

    float4 CO[3][4], CHL[3][4];
    #pragma unroll
    for (int k = 0; k < 4; ++k) {
        CO[0][k] = *(const float4*)(SCo + (size_t)(k)     * RS);
        CO[1][k] = *(const float4*)(SCo + (size_t)(4 + k) * RS);
    }
    if (lane == 0) {
        #pragma unroll
        for (int k = 0; k < 4; ++k) {
            CHL[0][k] = *(const float4*)(SCh + (size_t)(k)     * HST);
            CHL[1][k] = *(const float4*)(SCh + (size_t)(4 + k) * HST);
        }
    }

    for (int db = 0; db < 2064; db += 24) {
        #pragma unroll
        for (int u = 0; u < 6; ++u) {
            const int cur = u % 3;
            const int pre = (u + 2) % 3;
            int dpre = db + 4 * u + 8;
            #pragma unroll
            for (int k = 0; k < 4; ++k)
                CO[pre][k] = *(const float4*)(SCo + (size_t)(dpre + k) * RS);
            if (lane == 0) {
                #pragma unroll
                for (int k = 0; k < 4; ++k)
                    CHL[pre][k] = *(const float4*)(SCh + (size_t)(dpre + k) * HST);
            }
            if (u % 2 == 0)
                superstep(db + 4 * u, t, lane, CO[cur], CHL[cur], p, q,
                          &sp[0][0], &sq[0][0], &sp[1][0], &sq[1][0], res);
            else
                superstep(db + 4 * u, t, lane, CO[cur], CHL[cur], p, q,
                          &sp[1][0], &sq[1][0], &sp[0][0], &sq[0][0], res);
        }
    }

    if (t == 255) g_bdist[b] = res;
}

// ---------------------------------------------------------------------------
// Kernel 4: mean over batches.
// ---------------------------------------------------------------------------
__global__ void reduce_kernel(float* out) {
    float v = g_bdist[threadIdx.x];
    #pragma unroll
    for (int o = 16; o > 0; o >>= 1) v += __shfl_down_sync(0xffffffffu, v, o);
    if (threadIdx.x == 0) out[0] = v * (1.0f / BB);
}

// ---------------------------------------------------------------------------
extern "C" void kernel_launch(void* const* d_in, const int* in_sizes, int n_in,
                              void* d_out, int out_size) {
    const float* pred = (const float*)d_in[0];
    const float* targ = (const float*)d_in[1];
    (void)in_sizes; (void)n_in; (void)out_size;

    dim3 ig(DROWS, BB);
    init_kernel<<<ig, 256>>>();
    norms_kernel<<<8192, 256>>>(pred, targ);
    dim3 cg(8, 8, 32);
    cost_kernel<<<cg, 256>>>(pred, targ);
    dp_kernel<<<32, 256>>>();
    reduce_kernel<<<1, 32>>>((float*)d_out);
}